// round 1
// baseline (speedup 1.0000x reference)
#include <cuda_runtime.h>

#define BB 2
#define MM 4
#define CCH 64
#define VV 110592
#define KK 4
#define CB 8            // channels per block in main kernel
#define CG (CCH/CB)     // 8 channel groups
#define VS 9            // V splits in main kernel
#define VCHUNK (VV/VS)  // 12288
#define SPLITA 27
#define CHUNKA (VV/SPLITA) // 4096
#define EPSL 1e-6f

// ---- scratch (no allocations allowed) ----
__device__ float g_numpart[BB*MM*CG*VS*CB*KK];   // 576 blocks * 32 values
__device__ float g_twpart[BB*SPLITA*MM*KK];      // 54 * 16
__device__ float g_cntpart[BB*SPLITA*KK];        // 54 * 4
__device__ unsigned char g_t8[BB*VV];
__device__ int g_is64;

// Detect whether target buffer is int64 (odd 32-bit words all zero) or int32.
__global__ void kdetect(const int* __restrict__ tgt_words) {
    __shared__ int s_any;
    if (threadIdx.x == 0) s_any = 0;
    __syncthreads();
    int any = 0;
    // scan first 2048 words (within bounds for both dtypes: >= V words exist)
    for (int i = threadIdx.x; i < 1024; i += blockDim.x) {
        any |= tgt_words[2*i + 1];
    }
    if (any) atomicOr(&s_any, 1);
    __syncthreads();
    if (threadIdx.x == 0) g_is64 = (s_any == 0) ? 1 : 0;
}

// Prep: convert target->uint8, per-(b,m,k) weighted mass partials, per-(b,k) counts.
__global__ __launch_bounds__(256) void kprep(const int* __restrict__ tgt_words,
                                             const float* __restrict__ w) {
    int b = blockIdx.x;       // 0..1
    int sa = blockIdx.y;      // 0..26
    int v0 = sa * CHUNKA;
    const int is64 = g_is64;
    unsigned char* t8 = g_t8 + (long)b * VV + v0;
    const int* tw_words = tgt_words;  // words
    float twl[MM*KK];
    float cl[KK];
#pragma unroll
    for (int i = 0; i < MM*KK; i++) twl[i] = 0.f;
#pragma unroll
    for (int i = 0; i < KK; i++) cl[i] = 0.f;

    for (int i = threadIdx.x; i < CHUNKA; i += 256) {
        long v = (long)b * VV + v0 + i;
        int t = is64 ? tw_words[2*v] : tw_words[v];
        t8[i] = (unsigned char)t;
#pragma unroll
        for (int k = 0; k < KK; k++) cl[k] += (t == k) ? 1.f : 0.f;
#pragma unroll
        for (int m = 0; m < MM; m++) {
            float wv = w[((long)(b*MM + m))*VV + v0 + i];
#pragma unroll
            for (int k = 0; k < KK; k++) twl[m*KK + k] += (t == k) ? wv : 0.f;
        }
    }

    // reduce 20 values across block
    float vals[20];
#pragma unroll
    for (int j = 0; j < 16; j++) vals[j] = twl[j];
#pragma unroll
    for (int j = 0; j < 4; j++) vals[16 + j] = cl[j];
#pragma unroll
    for (int j = 0; j < 20; j++) {
#pragma unroll
        for (int off = 16; off > 0; off >>= 1)
            vals[j] += __shfl_down_sync(0xffffffffu, vals[j], off);
    }
    __shared__ float sred[8][20];
    int lane = threadIdx.x & 31, wid = threadIdx.x >> 5;
    if (lane == 0) {
#pragma unroll
        for (int j = 0; j < 20; j++) sred[wid][j] = vals[j];
    }
    __syncthreads();
    if (threadIdx.x < 20) {
        int j = threadIdx.x;
        float s = 0.f;
#pragma unroll
        for (int ww = 0; ww < 8; ww++) s += sred[ww][j];
        if (j < 16) g_twpart[(b*SPLITA + sa)*16 + j] = s;
        else        g_cntpart[(b*SPLITA + sa)*4 + (j - 16)] = s;
    }
}

// Main kernel: num[b][m][k][c] partial sums. One block = (bm, cgroup, vsplit).
__global__ __launch_bounds__(256) void knum(const float* __restrict__ f,
                                            const float* __restrict__ w) {
    int bm = blockIdx.x;   // 0..7  (b*4+m)
    int cg = blockIdx.y;   // 0..7
    int vs = blockIdx.z;   // 0..8
    int b = bm >> 2;
    long vbase = (long)vs * VCHUNK;
    const float* fb = f + ((long)bm * CCH + cg * CB) * VV + vbase;
    const float* wb = w + (long)bm * VV + vbase;
    const unsigned char* tb = g_t8 + (long)b * VV + vbase;

    float acc[CB][KK];
#pragma unroll
    for (int cc = 0; cc < CB; cc++)
#pragma unroll
        for (int k = 0; k < KK; k++) acc[cc][k] = 0.f;

    int tid = threadIdx.x;
#pragma unroll 1
    for (int i = 0; i < VCHUNK / (256 * 4); i++) {   // 12 iterations
        int v = (i * 256 + tid) * 4;
        float4 wv = *(const float4*)(wb + v);
        uchar4 tv = *(const uchar4*)(tb + v);
        int   ts[4] = { tv.x, tv.y, tv.z, tv.w };
        float ws[4] = { wv.x, wv.y, wv.z, wv.w };
        float msk[4][KK];
#pragma unroll
        for (int j = 0; j < 4; j++)
#pragma unroll
            for (int k = 0; k < KK; k++)
                msk[j][k] = (ts[j] == k) ? ws[j] : 0.f;
#pragma unroll
        for (int cc = 0; cc < CB; cc++) {
            float4 fv = *(const float4*)(fb + (long)cc * VV + v);
            float fs[4] = { fv.x, fv.y, fv.z, fv.w };
#pragma unroll
            for (int k = 0; k < KK; k++) {
                acc[cc][k] += fs[0] * msk[0][k];
                acc[cc][k] += fs[1] * msk[1][k];
                acc[cc][k] += fs[2] * msk[2][k];
                acc[cc][k] += fs[3] * msk[3][k];
            }
        }
    }

    // warp reduce all 32 accumulators
#pragma unroll
    for (int cc = 0; cc < CB; cc++)
#pragma unroll
        for (int k = 0; k < KK; k++) {
#pragma unroll
            for (int off = 16; off > 0; off >>= 1)
                acc[cc][k] += __shfl_down_sync(0xffffffffu, acc[cc][k], off);
        }
    __shared__ float sred[8][32];
    int lane = tid & 31, wid = tid >> 5;
    if (lane == 0) {
#pragma unroll
        for (int cc = 0; cc < CB; cc++)
#pragma unroll
            for (int k = 0; k < KK; k++) sred[wid][cc*KK + k] = acc[cc][k];
    }
    __syncthreads();
    if (tid < 32) {
        float s = 0.f;
#pragma unroll
        for (int ww = 0; ww < 8; ww++) s += sred[ww][tid];
        g_numpart[((bm*CG + cg)*VS + vs)*32 + tid] = s;
    }
}

// Finalize: prototypes, normalization, pairwise sims, scalar loss.
__global__ __launch_bounds__(1024) void kfin(float* __restrict__ out) {
    __shared__ float s_proto[32 * 64];   // row = bm*4+k
    __shared__ float s_tw[32];           // (+EPS)
    __shared__ float s_cnt[8];           // [b][k]
    __shared__ float s_aterm[48], s_acnt[48], s_sterm[48], s_scnt[48];
    int tid = threadIdx.x;

    if (tid < 32) {
        int bm = tid >> 2, k = tid & 3;
        int b = bm >> 2, m = bm & 3;
        float s = 0.f;
        for (int sa = 0; sa < SPLITA; sa++)
            s += g_twpart[(b*SPLITA + sa)*16 + m*4 + k];
        s_tw[tid] = s + EPSL;
    } else if (tid < 40) {
        int j = tid - 32;
        int b = j >> 2, k = j & 3;
        float s = 0.f;
        for (int sa = 0; sa < SPLITA; sa++)
            s += g_cntpart[(b*SPLITA + sa)*4 + k];
        s_cnt[j] = s;
    }
    __syncthreads();

    // proto raw = num / tw
    for (int cell = tid; cell < 2048; cell += 1024) {
        int bm = cell >> 8;
        int rem = cell & 255;
        int c = rem >> 2, k = rem & 3;
        int cg = c >> 3, cc = c & 7;
        float s = 0.f;
        for (int vs = 0; vs < VS; vs++)
            s += g_numpart[((bm*CG + cg)*VS + vs)*32 + cc*4 + k];
        s_proto[(bm*4 + k)*64 + c] = s / s_tw[bm*4 + k];
    }
    __syncthreads();

    // normalize: warp g owns row g
    int lane = tid & 31, wid = tid >> 5;
    {
        float v1 = s_proto[wid*64 + lane];
        float v2 = s_proto[wid*64 + lane + 32];
        float ss = v1*v1 + v2*v2;
#pragma unroll
        for (int off = 16; off > 0; off >>= 1)
            ss += __shfl_xor_sync(0xffffffffu, ss, off);
        float norm = sqrtf(fmaxf(ss, 1e-24f));
        norm = fmaxf(norm, 1e-12f);
        float inv = 1.f / norm;
        s_proto[wid*64 + lane]      = v1 * inv;
        s_proto[wid*64 + lane + 32] = v2 * inv;
    }
    __syncthreads();

    // 96 pair dot products: warp handles p = wid, wid+32, wid+64
    const int p1t[6] = {0,0,0,1,1,2};
    const int p2t[6] = {1,2,3,2,3,3};
    for (int p = wid; p < 96; p += 32) {
        int r1, r2, outidx;
        bool val;
        bool isAlign = (p < 48);
        float om = 1.f;
        if (isAlign) {
            int pa = p;
            int b = pa / 24; int rem = pa % 24;
            int mp = rem >> 2, k = rem & 3;
            int m = p1t[mp], n = p2t[mp];
            r1 = (b*4 + m)*4 + k;
            r2 = (b*4 + n)*4 + k;
            val = (s_cnt[b*4 + k] >= 1.f) && (k != 0);
            float cd = s_cnt[b*4 + k] + EPSL;
            om = (s_tw[r1] / cd) * (s_tw[r2] / cd);
            outidx = pa;
        } else {
            int ps = p - 48;
            int b = ps / 24; int rem = ps % 24;
            int m = rem / 6, kp = rem % 6;
            int k1 = p1t[kp], k2 = p2t[kp];
            r1 = (b*4 + m)*4 + k1;
            r2 = (b*4 + m)*4 + k2;
            val = (s_cnt[b*4 + k1] >= 1.f) && (k1 != 0) &&
                  (s_cnt[b*4 + k2] >= 1.f) && (k2 != 0);
            outidx = ps;
        }
        float a1 = s_proto[r1*64 + lane],      b1 = s_proto[r2*64 + lane];
        float a2 = s_proto[r1*64 + lane + 32], b2 = s_proto[r2*64 + lane + 32];
        float dot = a1*b1 + a2*b2;
#pragma unroll
        for (int off = 16; off > 0; off >>= 1)
            dot += __shfl_xor_sync(0xffffffffu, dot, off);
        if (lane == 0) {
            if (isAlign) {
                s_aterm[outidx] = val ? om * fmaxf(0.9f - dot, 0.f) : 0.f;
                s_acnt[outidx]  = val ? 1.f : 0.f;
            } else {
                s_sterm[outidx] = val ? fmaxf(dot - 0.1f, 0.f) : 0.f;
                s_scnt[outidx]  = val ? 1.f : 0.f;
            }
        }
    }
    __syncthreads();
    if (tid == 0) {
        float as = 0.f, ac = 0.f, ssum = 0.f, sc = 0.f;
        for (int i = 0; i < 48; i++) { as += s_aterm[i]; ac += s_acnt[i]; }
        for (int i = 0; i < 48; i++) { ssum += s_sterm[i]; sc += s_scnt[i]; }
        out[0] = as / (ac + EPSL) + ssum / (sc + EPSL);
    }
}

extern "C" void kernel_launch(void* const* d_in, const int* in_sizes, int n_in,
                              void* d_out, int out_size) {
    const float* feats   = (const float*)d_in[0];
    const float* weights = (const float*)d_in[1];
    const int*   tgt_w   = (const int*)d_in[2];   // int32 or int64 words; detected
    float* out = (float*)d_out;

    kdetect<<<1, 256>>>(tgt_w);
    kprep<<<dim3(BB, SPLITA), 256>>>(tgt_w, weights);
    knum<<<dim3(BB*MM, CG, VS), 256>>>(feats, weights);
    kfin<<<1, 1024>>>(out);
}

// round 2
// speedup vs baseline: 1.0393x; 1.0393x over previous
#include <cuda_runtime.h>

#define BB 2
#define MM 4
#define CCH 64
#define VV 110592
#define KK 4
#define CB 8            // channels per block
#define CG 8            // channel groups
#define VS 18           // V splits
#define VCHUNK (VV/VS)  // 6144
#define NBLK (BB*MM*CG*VS)  // 1152
#define EPSL 1e-6f

// ---- scratch (no allocations allowed) ----
__device__ float g_numpart[NBLK * 32];         // per-block (cc,k) partials
__device__ float g_twpart[BB*MM*VS*KK];        // (bm, vs, k)
__device__ float g_cntpart[BB*VS*KK];          // (b, vs, k)
__device__ unsigned g_ctr;                     // zero-init; reset at end of each launch

__global__ __launch_bounds__(256) void kmain(const float* __restrict__ f,
                                             const float* __restrict__ w,
                                             const int*   __restrict__ tw_words,
                                             float* __restrict__ out) {
    const int bm = blockIdx.x;   // 0..7 (b*4+m)
    const int cg = blockIdx.y;   // 0..7
    const int vs = blockIdx.z;   // 0..17
    const int b  = bm >> 2;
    const int tid = threadIdx.x;
    const int lane = tid & 31, wid = tid >> 5;

    __shared__ float sred[8][32];
    __shared__ float s_proto[2048];
    __shared__ float s_tw[32];
    __shared__ float s_cnt[8];
    __shared__ float s_aterm[48], s_acnt[48], s_sterm[48], s_scnt[48];
    __shared__ int   s_last;

    // ---- dtype detect: every block scans the SAME first 2048 high-words ----
    // (in-bounds for both dtypes; verdict identical across blocks)
    int any = 0;
    for (int i = tid; i < 2048; i += 256) any |= tw_words[2*i + 1];
    const int is64 = (__syncthreads_or(any) == 0);

    const long vbase = (long)vs * VCHUNK;
    const float* fb = f + ((long)bm*CCH + (long)cg*CB)*VV + vbase;
    const float* wb = w + (long)bm*VV + vbase;
    const long  ebase = (long)b*VV + vbase;

    float acc[CB][KK];
#pragma unroll
    for (int cc = 0; cc < CB; cc++)
#pragma unroll
        for (int k = 0; k < KK; k++) acc[cc][k] = 0.f;
    float twl[KK] = {0.f,0.f,0.f,0.f};
    float cl [KK] = {0.f,0.f,0.f,0.f};
    const bool doTW  = (cg == 0);
    const bool doCNT = doTW && ((bm & 3) == 0);

#pragma unroll 1
    for (int i = 0; i < VCHUNK/1024; i++) {   // 6 iterations
        const int v = (i*256 + tid)*4;
        // --- batch all loads up front for MLP ---
        float4 wv = *(const float4*)(wb + v);
        int t0,t1,t2,t3;
        {
            long e = ebase + v;
            if (is64) {
                const int4* p = (const int4*)tw_words + (e >> 1);
                int4 q0 = p[0], q1 = p[1];
                t0 = q0.x; t1 = q0.z; t2 = q1.x; t3 = q1.z;
            } else {
                int4 q = ((const int4*)tw_words)[e >> 2];
                t0 = q.x; t1 = q.y; t2 = q.z; t3 = q.w;
            }
        }
        float4 fv[CB];
#pragma unroll
        for (int cc = 0; cc < CB; cc++)
            fv[cc] = *(const float4*)(fb + (long)cc*VV + v);

        const int   ts[4] = { t0, t1, t2, t3 };
        const float ws[4] = { wv.x, wv.y, wv.z, wv.w };
        float msk[4][KK];
#pragma unroll
        for (int j = 0; j < 4; j++)
#pragma unroll
            for (int k = 0; k < KK; k++)
                msk[j][k] = (ts[j] == k) ? ws[j] : 0.f;

        if (doTW) {
#pragma unroll
            for (int k = 0; k < KK; k++)
                twl[k] += (msk[0][k] + msk[1][k]) + (msk[2][k] + msk[3][k]);
        }
        if (doCNT) {
#pragma unroll
            for (int k = 0; k < KK; k++) {
                float c0 = (t0==k)?1.f:0.f, c1 = (t1==k)?1.f:0.f;
                float c2 = (t2==k)?1.f:0.f, c3 = (t3==k)?1.f:0.f;
                cl[k] += (c0+c1)+(c2+c3);
            }
        }
#pragma unroll
        for (int cc = 0; cc < CB; cc++) {
            const float fs[4] = { fv[cc].x, fv[cc].y, fv[cc].z, fv[cc].w };
#pragma unroll
            for (int k = 0; k < KK; k++) {
                acc[cc][k] += fs[0]*msk[0][k];
                acc[cc][k] += fs[1]*msk[1][k];
                acc[cc][k] += fs[2]*msk[2][k];
                acc[cc][k] += fs[3]*msk[3][k];
            }
        }
    }

    // ---- block-reduce 32 accumulators ----
#pragma unroll
    for (int cc = 0; cc < CB; cc++)
#pragma unroll
        for (int k = 0; k < KK; k++)
#pragma unroll
            for (int off = 16; off > 0; off >>= 1)
                acc[cc][k] += __shfl_down_sync(0xffffffffu, acc[cc][k], off);
    if (lane == 0) {
#pragma unroll
        for (int cc = 0; cc < CB; cc++)
#pragma unroll
            for (int k = 0; k < KK; k++) sred[wid][cc*KK + k] = acc[cc][k];
    }
    __syncthreads();
    const int bid = (bm*CG + cg)*VS + vs;
    if (tid < 32) {
        float s = 0.f;
#pragma unroll
        for (int ww = 0; ww < 8; ww++) s += sred[ww][tid];
        g_numpart[bid*32 + tid] = s;
    }
    __syncthreads();

    // ---- block-reduce tw/cnt (8 values) ----
    {
        float vals[8];
#pragma unroll
        for (int j = 0; j < 4; j++) { vals[j] = twl[j]; vals[4+j] = cl[j]; }
#pragma unroll
        for (int j = 0; j < 8; j++)
#pragma unroll
            for (int off = 16; off > 0; off >>= 1)
                vals[j] += __shfl_down_sync(0xffffffffu, vals[j], off);
        if (lane == 0) {
#pragma unroll
            for (int j = 0; j < 8; j++) sred[wid][j] = vals[j];
        }
        __syncthreads();
        if (tid < 8) {
            float s = 0.f;
#pragma unroll
            for (int ww = 0; ww < 8; ww++) s += sred[ww][tid];
            if (tid < 4) {
                if (doTW) g_twpart[(bm*VS + vs)*4 + tid] = s;
            } else {
                if (doCNT) g_cntpart[(b*VS + vs)*4 + (tid-4)] = s;
            }
        }
    }

    // ---- last-block-done finalize ----
    __threadfence();
    __syncthreads();
    if (tid == 0) {
        unsigned old = atomicAdd(&g_ctr, 1u);
        s_last = (old == (unsigned)(NBLK - 1));
    }
    __syncthreads();
    if (!s_last) return;

    // Phase A: tw (32) + cnt (8)
    if (tid < 32) {
        int bm_ = tid >> 2, k = tid & 3;
        float s = 0.f;
        for (int v = 0; v < VS; v++) s += g_twpart[(bm_*VS + v)*4 + k];
        s_tw[tid] = s + EPSL;
    } else if (tid < 40) {
        int j = tid - 32, b_ = j >> 2, k = j & 3;
        float s = 0.f;
        for (int v = 0; v < VS; v++) s += g_cntpart[(b_*VS + v)*4 + k];
        s_cnt[j] = s;
    }
    __syncthreads();

    // Phase B: proto raw = num / tw
    for (int cell = tid; cell < 2048; cell += 256) {
        int bm_ = cell >> 8;
        int rem = cell & 255;
        int c = rem >> 2, k = rem & 3;
        int cg_ = c >> 3, cc = c & 7;
        float s = 0.f;
        for (int v = 0; v < VS; v++)
            s += g_numpart[((bm_*CG + cg_)*VS + v)*32 + cc*4 + k];
        s_proto[(bm_*4 + k)*64 + c] = s / s_tw[bm_*4 + k];
    }
    __syncthreads();

    // Phase C: normalize 32 rows (8 warps x 4 rows)
#pragma unroll
    for (int j = 0; j < 4; j++) {
        int r = wid + 8*j;
        float v1 = s_proto[r*64 + lane];
        float v2 = s_proto[r*64 + lane + 32];
        float ss = v1*v1 + v2*v2;
#pragma unroll
        for (int off = 16; off > 0; off >>= 1)
            ss += __shfl_xor_sync(0xffffffffu, ss, off);
        float norm = fmaxf(sqrtf(fmaxf(ss, 1e-24f)), 1e-12f);
        float inv = 1.f / norm;
        s_proto[r*64 + lane]      = v1 * inv;
        s_proto[r*64 + lane + 32] = v2 * inv;
    }
    __syncthreads();

    // Phase D: 96 pair dot products (8 warps x 12 pairs)
    {
        const int p1t[6] = {0,0,0,1,1,2};
        const int p2t[6] = {1,2,3,2,3,3};
        for (int p = wid; p < 96; p += 8) {
            int r1, r2, outidx;
            bool val;
            bool isAlign = (p < 48);
            float om = 1.f;
            if (isAlign) {
                int pa = p;
                int b_ = pa / 24; int rem = pa % 24;
                int mp = rem >> 2, k = rem & 3;
                int m = p1t[mp], n = p2t[mp];
                r1 = (b_*4 + m)*4 + k;
                r2 = (b_*4 + n)*4 + k;
                val = (s_cnt[b_*4 + k] >= 1.f) && (k != 0);
                float cd = s_cnt[b_*4 + k] + EPSL;
                om = (s_tw[r1] / cd) * (s_tw[r2] / cd);
                outidx = pa;
            } else {
                int ps = p - 48;
                int b_ = ps / 24; int rem = ps % 24;
                int m = rem / 6, kp = rem % 6;
                int k1 = p1t[kp], k2 = p2t[kp];
                r1 = (b_*4 + m)*4 + k1;
                r2 = (b_*4 + m)*4 + k2;
                val = (s_cnt[b_*4 + k1] >= 1.f) && (k1 != 0) &&
                      (s_cnt[b_*4 + k2] >= 1.f) && (k2 != 0);
                outidx = ps;
            }
            float a1 = s_proto[r1*64 + lane],      b1 = s_proto[r2*64 + lane];
            float a2 = s_proto[r1*64 + lane + 32], b2 = s_proto[r2*64 + lane + 32];
            float dot = a1*b1 + a2*b2;
#pragma unroll
            for (int off = 16; off > 0; off >>= 1)
                dot += __shfl_xor_sync(0xffffffffu, dot, off);
            if (lane == 0) {
                if (isAlign) {
                    s_aterm[outidx] = val ? om * fmaxf(0.9f - dot, 0.f) : 0.f;
                    s_acnt[outidx]  = val ? 1.f : 0.f;
                } else {
                    s_sterm[outidx] = val ? fmaxf(dot - 0.1f, 0.f) : 0.f;
                    s_scnt[outidx]  = val ? 1.f : 0.f;
                }
            }
        }
    }
    __syncthreads();

    // Phase E: scalar loss + counter reset
    if (tid == 0) {
        float as = 0.f, ac = 0.f, ssum = 0.f, sc = 0.f;
        for (int i = 0; i < 48; i++) { as += s_aterm[i]; ac += s_acnt[i]; }
        for (int i = 0; i < 48; i++) { ssum += s_sterm[i]; sc += s_scnt[i]; }
        out[0] = as / (ac + EPSL) + ssum / (sc + EPSL);
        g_ctr = 0;   // ready for next graph replay
    }
}

extern "C" void kernel_launch(void* const* d_in, const int* in_sizes, int n_in,
                              void* d_out, int out_size) {
    const float* feats   = (const float*)d_in[0];
    const float* weights = (const float*)d_in[1];
    const int*   tgt_w   = (const int*)d_in[2];   // int32 or int64; detected on-device
    float* out = (float*)d_out;

    kmain<<<dim3(BB*MM, CG, VS), 256>>>(feats, weights, tgt_w, out);
}